// round 6
// baseline (speedup 1.0000x reference)
#include <cuda_runtime.h>
#include <math.h>
#include <stdint.h>

typedef unsigned long long ull;

// ---------------------------------------------------------------- constants
constexpr int BATCH = 64;
constexpr int SEQ   = 512;
constexpr int WIDTH = 256;   // hidden width
constexpr int EMBED = 512;   // 2*WIDTH
constexpr int ROWS  = BATCH * SEQ;   // 32768 GEMM rows

// ---------------------------------------------------------------- scratch
__device__ float g_bufA[BATCH * SEQ * WIDTH];
__device__ float g_bufB[BATCH * SEQ * WIDTH];

// ---------------------------------------------------------------- f32x2 helpers
__device__ __forceinline__ ull pk2(float lo, float hi) {
    ull r; asm("mov.b64 %0,{%1,%2};" : "=l"(r) : "f"(lo), "f"(hi)); return r;
}
__device__ __forceinline__ void up2(ull v, float& lo, float& hi) {
    asm("mov.b64 {%0,%1},%2;" : "=f"(lo), "=f"(hi) : "l"(v));
}
__device__ __forceinline__ ull ffma2(ull a, ull b, ull c) {
    ull d; asm("fma.rn.f32x2 %0,%1,%2,%3;" : "=l"(d) : "l"(a), "l"(b), "l"(c)); return d;
}
__device__ __forceinline__ uint32_t smem_u32(const void* p) {
    uint32_t a;
    asm("{ .reg .u64 t; cvta.to.shared.u64 t, %1; cvt.u32.u64 %0, t; }"
        : "=r"(a) : "l"(p));
    return a;
}

// ============================================================================
// GEMM: C[R, 256] = A[R, K] @ Wm[K, 256] + bias   (unchanged, known-good)
// ============================================================================
template<bool GATHER>
__global__ void __launch_bounds__(512, 1)
gemm_kernel(const int* __restrict__ tokens, const float* __restrict__ A,
            const float* __restrict__ Wm, const float* __restrict__ bias,
            float* __restrict__ C, int K)
{
    __shared__ ull   ATu[16][128];
    __shared__ float Bs[16][128];

    const int tid = threadIdx.x;
    const int r0  = blockIdx.x * 128;
    const int n0  = blockIdx.y * 128;

    const int lrow = tid >> 2;
    const int lkq  = (tid & 3) * 4;
    const float* arow;
    if (GATHER) arow = A + (size_t)tokens[r0 + lrow] * (size_t)K;
    else        arow = A + (size_t)(r0 + lrow) * (size_t)K;

    const int bn = (tid & 31) * 4;
    const int bk = tid >> 5;

    const int ty = tid >> 5;
    const int tx = tid & 31;
    const int cm = ty * 8;
    const int cn = tx * 4;

    ull acc[8][2];
    #pragma unroll
    for (int r = 0; r < 8; r++) { acc[r][0] = 0ull; acc[r][1] = 0ull; }

    #pragma unroll 1
    for (int k0 = 0; k0 < K; k0 += 16) {
        float4 a4 = *(const float4*)(arow + k0 + lkq);
        float4 b4 = *(const float4*)(Wm + (size_t)(k0 + bk) * WIDTH + n0 + bn);
        __syncthreads();
        ATu[lkq + 0][lrow] = pk2(a4.x, a4.x);
        ATu[lkq + 1][lrow] = pk2(a4.y, a4.y);
        ATu[lkq + 2][lrow] = pk2(a4.z, a4.z);
        ATu[lkq + 3][lrow] = pk2(a4.w, a4.w);
        *(float4*)&Bs[bk][bn] = b4;
        __syncthreads();

        #pragma unroll
        for (int kk = 0; kk < 16; kk++) {
            ulonglong2 bv = *(const ulonglong2*)&Bs[kk][cn];
            #pragma unroll
            for (int r = 0; r < 8; r++) {
                ull ad = ATu[kk][cm + r];
                acc[r][0] = ffma2(ad, bv.x, acc[r][0]);
                acc[r][1] = ffma2(ad, bv.y, acc[r][1]);
            }
        }
    }

    const float bv0 = bias[n0 + cn + 0];
    const float bv1 = bias[n0 + cn + 1];
    const float bv2 = bias[n0 + cn + 2];
    const float bv3 = bias[n0 + cn + 3];
    #pragma unroll
    for (int r = 0; r < 8; r++) {
        float c0, c1, c2, c3;
        up2(acc[r][0], c0, c1);
        up2(acc[r][1], c2, c3);
        float4 o = make_float4(c0 + bv0, c1 + bv1, c2 + bv2, c3 + bv3);
        *(float4*)&C[(size_t)(r0 + cm + r) * WIDTH + n0 + cn] = o;
    }
}

// ============================================================================
// RNN scan: cluster of 2 CTAs per batch row, 512 threads per CTA.
//  - CTA rank owns output columns [rank*128, rank*128+128)
//  - thread: column jl = tid>>2 (j = rank*128+jl), k-quarter sub = tid&3
//  - each thread's 32 U pairs (64 k-values) live entirely in REGISTERS
//  - h (all 256 cols) triple-buffered in smem; local half via STS +
//    __syncthreads, peer half via st.shared::cluster + per-lane remote
//    mbarrier.arrive.release.cluster (128 arrives/step, self-ordered)
// ============================================================================
constexpr int HSTR = 264;    // floats per h buffer (256 + pad, 16B multiple)

template<bool WRITE_SEQ, bool FINAL>
__global__ void __launch_bounds__(512, 1) __cluster_dims__(2, 1, 1)
rnn_kernel(const float* __restrict__ xw, const float* __restrict__ U,
           float* __restrict__ hs, const float* __restrict__ Wd,
           const float* __restrict__ bd, float* __restrict__ out)
{
    __shared__ __align__(16) float hbuf[3][HSTR];
    __shared__ __align__(8)  ull mbars[2];
    __shared__ float red[2 * WIDTH];

    const int tid = threadIdx.x;
    uint32_t rank;
    asm("mov.u32 %0, %%cluster_ctarank;" : "=r"(rank));
    const int b   = blockIdx.x >> 1;
    const int sub = tid & 3;              // k-quarter
    const int jl  = tid >> 2;             // local column 0..127
    const int j   = (int)rank * 128 + jl; // global column
    const int kb  = sub * 64;             // k range base (64 k-values)

    // ---- this thread's 32 U pairs, all in registers
    ull ureg[32];
    #pragma unroll
    for (int m = 0; m < 32; m++)
        ureg[m] = pk2(U[(size_t)(kb + 2 * m) * WIDTH + j],
                      U[(size_t)(kb + 2 * m + 1) * WIDTH + j]);

    // ---- init: zero h buffer 0, init mbars (expected = 128 remote arrives)
    for (int i = tid; i < HSTR; i += 512) hbuf[0][i] = 0.0f;
    if (tid == 0) {
        asm volatile("mbarrier.init.shared.b64 [%0], %1;"
                     :: "r"(smem_u32(&mbars[0])), "r"(128) : "memory");
        asm volatile("mbarrier.init.shared.b64 [%0], %1;"
                     :: "r"(smem_u32(&mbars[1])), "r"(128) : "memory");
    }
    __syncthreads();
    asm volatile("barrier.cluster.arrive.aligned;" ::: "memory");
    asm volatile("barrier.cluster.wait.aligned;" ::: "memory");

    const uint32_t hbuf_u32 = smem_u32(&hbuf[0][0]);
    const uint32_t mbar_u32 = smem_u32(&mbars[0]);
    uint32_t peer_hbuf, peer_mbar;
    {
        uint32_t pr = rank ^ 1u;
        asm("mapa.shared::cluster.u32 %0, %1, %2;" : "=r"(peer_hbuf) : "r"(hbuf_u32), "r"(pr));
        asm("mapa.shared::cluster.u32 %0, %1, %2;" : "=r"(peer_mbar) : "r"(mbar_u32), "r"(pr));
    }

    const float* xb = xw + (size_t)b * SEQ * WIDTH + j;
    float xt_next = xb[0];

    int rd = 0, wr = 1;   // mod-3 rotating buffers

    #pragma unroll 1
    for (int t = 0; t < SEQ; t++) {
        const float xt = xt_next;
        if (t + 1 < SEQ) xt_next = xb[(size_t)(t + 1) * WIDTH];

        const ull* hp = (const ull*)&hbuf[rd][0] + sub * 32;  // 32 pairs
        ull a0 = 0ull, a1 = 0ull, a2 = 0ull, a3 = 0ull;
        #pragma unroll
        for (int m = 0; m < 32; m += 4) {
            ulonglong2 h01 = *(const ulonglong2*)(hp + m);
            ulonglong2 h23 = *(const ulonglong2*)(hp + m + 2);
            a0 = ffma2(h01.x, ureg[m + 0], a0);
            a1 = ffma2(h01.y, ureg[m + 1], a1);
            a2 = ffma2(h23.x, ureg[m + 2], a2);
            a3 = ffma2(h23.y, ureg[m + 3], a3);
        }
        float s0, s1, s2, s3, s4, s5, s6, s7;
        up2(a0, s0, s1); up2(a1, s2, s3); up2(a2, s4, s5); up2(a3, s6, s7);
        float s = (((s0 + s1) + (s2 + s3)) + ((s4 + s5) + (s6 + s7)));
        // combine the 4 k-quarters (lanes 4jl..4jl+3)
        s += __shfl_xor_sync(0xFFFFFFFFu, s, 1);
        s += __shfl_xor_sync(0xFFFFFFFFu, s, 2);

        const float pre = xt + s;
        // fast tanh: 1 - 2/(e^{2x}+1)
        const float e  = __expf(2.0f * pre);
        const float hn = 1.0f - __fdividef(2.0f, e + 1.0f);

        const uint32_t mb_r = peer_mbar + (uint32_t)((t & 1) * 8);

        if (sub == 0) {
            hbuf[wr][j] = hn;                       // local copy (global col idx)
        } else if (sub == 1) {
            // remote copy into peer's buffer, then self-ordered release-arrive
            uint32_t raddr = peer_hbuf + (uint32_t)(wr * HSTR * 4 + j * 4);
            asm volatile("st.shared::cluster.f32 [%0], %1;"
                         :: "r"(raddr), "f"(hn) : "memory");
            asm volatile("mbarrier.arrive.release.cluster.shared::cluster.b64 _, [%0];"
                         :: "r"(mb_r) : "memory");
        } else if (WRITE_SEQ && sub == 2) {
            hs[(size_t)b * SEQ * WIDTH + (size_t)t * WIDTH + j] = hn;
        }

        __syncthreads();   // publishes local half (sub0 stores) to whole CTA

        // wait for peer's 128 remote arrives for this step
        {
            const uint32_t mb_l = mbar_u32 + (uint32_t)((t & 1) * 8);
            const uint32_t parity = (uint32_t)((t >> 1) & 1);
            uint32_t done;
            asm volatile(
                "{\n\t.reg .pred p;\n\t"
                "mbarrier.try_wait.parity.acquire.cluster.shared::cta.b64 p, [%1], %2;\n\t"
                "selp.b32 %0, 1, 0, p;\n\t}"
                : "=r"(done) : "r"(mb_l), "r"(parity) : "memory");
            if (!done) {
                asm volatile(
                    "{\n\t.reg .pred P1;\n\t"
                    "WL_%=:\n\t"
                    "mbarrier.try_wait.parity.acquire.cluster.shared::cta.b64 P1, [%0], %1, 0x989680;\n\t"
                    "@P1 bra.uni WD_%=;\n\t"
                    "bra.uni WL_%=;\n\t"
                    "WD_%=:\n\t}"
                    :: "r"(mb_l), "r"(parity) : "memory");
            }
        }

        rd = wr;
        wr = (wr == 2) ? 0 : wr + 1;
    }

    if (FINAL && rank == 0) {
        // full final h (both halves) lives in hbuf[rd]
        if (tid < 256) {
            const float h = hbuf[rd][tid];
            red[tid]         = h * Wd[tid * 2 + 0];
            red[WIDTH + tid] = h * Wd[tid * 2 + 1];
        }
        __syncthreads();
        #pragma unroll
        for (int sft = 128; sft > 0; sft >>= 1) {
            if (tid < sft) {
                red[tid]         += red[tid + sft];
                red[WIDTH + tid] += red[WIDTH + tid + sft];
            }
            __syncthreads();
        }
        if (tid == 0) {
            const float l0 = red[0] + bd[0];
            const float l1 = red[WIDTH] + bd[1];
            const float mx = fmaxf(l0, l1);
            const float e0 = expf(l0 - mx);
            const float e1 = expf(l1 - mx);
            const float inv = 1.0f / (e0 + e1);
            out[b * 2 + 0] = e0 * inv;
            out[b * 2 + 1] = e1 * inv;
        }
    }

    // no CTA exits while peer traffic into its smem may be in flight
    asm volatile("barrier.cluster.arrive.aligned;" ::: "memory");
    asm volatile("barrier.cluster.wait.aligned;" ::: "memory");
}

// ============================================================================
// launcher
// ============================================================================
extern "C" void kernel_launch(void* const* d_in, const int* in_sizes, int n_in,
                              void* d_out, int out_size)
{
    const int*   tokens = (const int*)  d_in[0];
    const float* emb    = (const float*)d_in[1];
    const float* W1     = (const float*)d_in[2];
    const float* U1     = (const float*)d_in[3];
    const float* b1     = (const float*)d_in[4];
    const float* W2     = (const float*)d_in[5];
    const float* U2     = (const float*)d_in[6];
    const float* b2     = (const float*)d_in[7];
    const float* Wd     = (const float*)d_in[8];
    const float* bd     = (const float*)d_in[9];
    float* out = (float*)d_out;

    float* bufA; cudaGetSymbolAddress((void**)&bufA, g_bufA);
    float* bufB; cudaGetSymbolAddress((void**)&bufB, g_bufB);

    dim3 ggrid(ROWS / 128, WIDTH / 128);   // (256, 2)

    // 1) xw1 = emb[tokens] @ W1 + b1  -> bufA
    gemm_kernel<true><<<ggrid, 512>>>(tokens, emb, W1, b1, bufA, EMBED);

    // 2) RNN1 scan (cluster-2 per row, 512 thr) -> h1 sequence in bufB
    rnn_kernel<true, false><<<2 * BATCH, 512>>>(bufA, U1, bufB,
                                                nullptr, nullptr, nullptr);

    // 3) xw2 = h1 @ W2 + b2 -> bufA
    gemm_kernel<false><<<ggrid, 512>>>(nullptr, bufB, W2, b2, bufA, WIDTH);

    // 4) RNN2 scan, fused dense + softmax -> out
    rnn_kernel<false, true><<<2 * BATCH, 512>>>(bufA, U2, nullptr,
                                                Wd, bd, out);

    (void)in_sizes; (void)n_in; (void)out_size;
}

// round 7
// speedup vs baseline: 2.0078x; 2.0078x over previous
#include <cuda_runtime.h>
#include <math.h>
#include <stdint.h>

typedef unsigned long long ull;

// ---------------------------------------------------------------- constants
constexpr int BATCH = 64;
constexpr int SEQ   = 512;
constexpr int WIDTH = 256;   // hidden width
constexpr int EMBED = 512;   // 2*WIDTH
constexpr int ROWS  = BATCH * SEQ;   // 32768 GEMM rows

// ---------------------------------------------------------------- scratch
__device__ float g_bufA[BATCH * SEQ * WIDTH];
__device__ float g_bufB[BATCH * SEQ * WIDTH];

// ---------------------------------------------------------------- f32x2 helpers
__device__ __forceinline__ ull pk2(float lo, float hi) {
    ull r; asm("mov.b64 %0,{%1,%2};" : "=l"(r) : "f"(lo), "f"(hi)); return r;
}
__device__ __forceinline__ void up2(ull v, float& lo, float& hi) {
    asm("mov.b64 {%0,%1},%2;" : "=f"(lo), "=f"(hi) : "l"(v));
}
__device__ __forceinline__ ull ffma2(ull a, ull b, ull c) {
    ull d; asm("fma.rn.f32x2 %0,%1,%2,%3;" : "=l"(d) : "l"(a), "l"(b), "l"(c)); return d;
}

// ============================================================================
// GEMM: C[R, 256] = A[R, K] @ Wm[K, 256] + bias   (unchanged, known-good)
// ============================================================================
template<bool GATHER>
__global__ void __launch_bounds__(512, 1)
gemm_kernel(const int* __restrict__ tokens, const float* __restrict__ A,
            const float* __restrict__ Wm, const float* __restrict__ bias,
            float* __restrict__ C, int K)
{
    __shared__ ull   ATu[16][128];
    __shared__ float Bs[16][128];

    const int tid = threadIdx.x;
    const int r0  = blockIdx.x * 128;
    const int n0  = blockIdx.y * 128;

    const int lrow = tid >> 2;
    const int lkq  = (tid & 3) * 4;
    const float* arow;
    if (GATHER) arow = A + (size_t)tokens[r0 + lrow] * (size_t)K;
    else        arow = A + (size_t)(r0 + lrow) * (size_t)K;

    const int bn = (tid & 31) * 4;
    const int bk = tid >> 5;

    const int ty = tid >> 5;
    const int tx = tid & 31;
    const int cm = ty * 8;
    const int cn = tx * 4;

    ull acc[8][2];
    #pragma unroll
    for (int r = 0; r < 8; r++) { acc[r][0] = 0ull; acc[r][1] = 0ull; }

    #pragma unroll 1
    for (int k0 = 0; k0 < K; k0 += 16) {
        float4 a4 = *(const float4*)(arow + k0 + lkq);
        float4 b4 = *(const float4*)(Wm + (size_t)(k0 + bk) * WIDTH + n0 + bn);
        __syncthreads();
        ATu[lkq + 0][lrow] = pk2(a4.x, a4.x);
        ATu[lkq + 1][lrow] = pk2(a4.y, a4.y);
        ATu[lkq + 2][lrow] = pk2(a4.z, a4.z);
        ATu[lkq + 3][lrow] = pk2(a4.w, a4.w);
        *(float4*)&Bs[bk][bn] = b4;
        __syncthreads();

        #pragma unroll
        for (int kk = 0; kk < 16; kk++) {
            ulonglong2 bv = *(const ulonglong2*)&Bs[kk][cn];
            #pragma unroll
            for (int r = 0; r < 8; r++) {
                ull ad = ATu[kk][cm + r];
                acc[r][0] = ffma2(ad, bv.x, acc[r][0]);
                acc[r][1] = ffma2(ad, bv.y, acc[r][1]);
            }
        }
    }

    const float bv0 = bias[n0 + cn + 0];
    const float bv1 = bias[n0 + cn + 1];
    const float bv2 = bias[n0 + cn + 2];
    const float bv3 = bias[n0 + cn + 3];
    #pragma unroll
    for (int r = 0; r < 8; r++) {
        float c0, c1, c2, c3;
        up2(acc[r][0], c0, c1);
        up2(acc[r][1], c2, c3);
        float4 o = make_float4(c0 + bv0, c1 + bv1, c2 + bv2, c3 + bv3);
        *(float4*)&C[(size_t)(r0 + cm + r) * WIDTH + n0 + cn] = o;
    }
}

// ============================================================================
// RNN scan, cluster-of-2 per batch row (R3 geometry), with the mbarrier
// protocol replaced by barrier.cluster (non-serializing, ~490cyc) and the
// h exchange done with plain DSMEM stores.
//  - rank owns output columns [rank*128, rank*128+128)
//  - 256 threads: column j = rank*128 + (tid>>1), k-half = tid&1
//  - 64 U pairs per thread, ALL in registers
//  - double-buffered h; barrier.cluster between steps orders peer stores
// ============================================================================
constexpr int HSTR = 264;

template<bool WRITE_SEQ, bool FINAL>
__global__ void __launch_bounds__(256, 1) __cluster_dims__(2, 1, 1)
rnn_kernel(const float* __restrict__ xw, const float* __restrict__ U,
           float* __restrict__ hs, const float* __restrict__ Wd,
           const float* __restrict__ bd, float* __restrict__ out)
{
    __shared__ __align__(16) float hbuf[2][HSTR];
    __shared__ float red[2 * WIDTH];

    const int tid = threadIdx.x;
    uint32_t rank;
    asm("mov.u32 %0, %%cluster_ctarank;" : "=r"(rank));
    const int b    = blockIdx.x >> 1;
    const int half = tid & 1;
    const int jl   = tid >> 1;             // 0..127
    const int j    = (int)rank * 128 + jl; // global column
    const int kb   = half * 128;

    // 64 U pairs in registers
    ull ureg[64];
    #pragma unroll
    for (int m = 0; m < 64; m++)
        ureg[m] = pk2(U[(size_t)(kb + 2 * m) * WIDTH + j],
                      U[(size_t)(kb + 2 * m + 1) * WIDTH + j]);

    for (int i = tid; i < 2 * HSTR; i += 256) ((float*)hbuf)[i] = 0.0f;
    __syncthreads();

    // peer smem address of hbuf
    uint32_t hbuf_u32;
    asm("{ .reg .u64 t; cvta.to.shared.u64 t, %1; cvt.u32.u64 %0, t; }"
        : "=r"(hbuf_u32) : "l"((const void*)&hbuf[0][0]));
    uint32_t peer_hbuf;
    {
        uint32_t pr = rank ^ 1u;
        asm("mapa.shared::cluster.u32 %0, %1, %2;" : "=r"(peer_hbuf) : "r"(hbuf_u32), "r"(pr));
    }

    asm volatile("barrier.cluster.arrive.aligned;" ::: "memory");
    asm volatile("barrier.cluster.wait.aligned;" ::: "memory");

    const float* xb = xw + (size_t)b * SEQ * WIDTH + j;
    float xt_next = xb[0];
    int rd = 0;

    #pragma unroll 1
    for (int t = 0; t < SEQ; t++) {
        const float xt = xt_next;
        if (t + 1 < SEQ) xt_next = xb[(size_t)(t + 1) * WIDTH];

        const ull* hp = (const ull*)&hbuf[rd][0] + half * 64;
        ull a0 = 0ull, a1 = 0ull, a2 = 0ull, a3 = 0ull;
        #pragma unroll
        for (int m = 0; m < 64; m += 4) {
            ulonglong2 h01 = *(const ulonglong2*)(hp + m);
            ulonglong2 h23 = *(const ulonglong2*)(hp + m + 2);
            a0 = ffma2(h01.x, ureg[m + 0], a0);
            a1 = ffma2(h01.y, ureg[m + 1], a1);
            a2 = ffma2(h23.x, ureg[m + 2], a2);
            a3 = ffma2(h23.y, ureg[m + 3], a3);
        }
        float s0, s1, s2, s3, s4, s5, s6, s7;
        up2(a0, s0, s1); up2(a1, s2, s3); up2(a2, s4, s5); up2(a3, s6, s7);
        float s = (((s0 + s1) + (s2 + s3)) + ((s4 + s5) + (s6 + s7)));
        s += __shfl_xor_sync(0xFFFFFFFFu, s, 1);

        const float e  = __expf(2.0f * (xt + s));
        const float hn = 1.0f - __fdividef(2.0f, e + 1.0f);

        const int wr = rd ^ 1;
        if (half == 0) {
            hbuf[wr][j] = hn;   // local copy at global column index
            // remote copy into peer buffer
            uint32_t raddr = peer_hbuf + (uint32_t)(wr * HSTR * 4 + j * 4);
            asm volatile("st.shared::cluster.f32 [%0], %1;"
                         :: "r"(raddr), "f"(hn) : "memory");
        } else if (WRITE_SEQ) {
            hs[(size_t)b * SEQ * WIDTH + (size_t)t * WIDTH + j] = hn;
        }

        // cluster barrier: orders ALL cluster-scope smem stores (local+remote)
        asm volatile("barrier.cluster.arrive.aligned;" ::: "memory");
        asm volatile("barrier.cluster.wait.aligned;" ::: "memory");
        rd = wr;
    }

    if (FINAL && rank == 0) {
        const float h = hbuf[rd][tid];
        red[tid]         = h * Wd[tid * 2 + 0];
        red[WIDTH + tid] = h * Wd[tid * 2 + 1];
        __syncthreads();
        #pragma unroll
        for (int sft = 128; sft > 0; sft >>= 1) {
            if (tid < sft) {
                red[tid]         += red[tid + sft];
                red[WIDTH + tid] += red[WIDTH + tid + sft];
            }
            __syncthreads();
        }
        if (tid == 0) {
            const float l0 = red[0] + bd[0];
            const float l1 = red[WIDTH] + bd[1];
            const float mx = fmaxf(l0, l1);
            const float e0 = expf(l0 - mx);
            const float e1 = expf(l1 - mx);
            const float inv = 1.0f / (e0 + e1);
            out[b * 2 + 0] = e0 * inv;
            out[b * 2 + 1] = e1 * inv;
        }
    }

    asm volatile("barrier.cluster.arrive.aligned;" ::: "memory");
    asm volatile("barrier.cluster.wait.aligned;" ::: "memory");
}

// ============================================================================
// launcher
// ============================================================================
extern "C" void kernel_launch(void* const* d_in, const int* in_sizes, int n_in,
                              void* d_out, int out_size)
{
    const int*   tokens = (const int*)  d_in[0];
    const float* emb    = (const float*)d_in[1];
    const float* W1     = (const float*)d_in[2];
    const float* U1     = (const float*)d_in[3];
    const float* b1     = (const float*)d_in[4];
    const float* W2     = (const float*)d_in[5];
    const float* U2     = (const float*)d_in[6];
    const float* b2     = (const float*)d_in[7];
    const float* Wd     = (const float*)d_in[8];
    const float* bd     = (const float*)d_in[9];
    float* out = (float*)d_out;

    float* bufA; cudaGetSymbolAddress((void**)&bufA, g_bufA);
    float* bufB; cudaGetSymbolAddress((void**)&bufB, g_bufB);

    dim3 ggrid(ROWS / 128, WIDTH / 128);   // (256, 2)

    gemm_kernel<true><<<ggrid, 512>>>(tokens, emb, W1, b1, bufA, EMBED);
    rnn_kernel<true, false><<<2 * BATCH, 256>>>(bufA, U1, bufB,
                                                nullptr, nullptr, nullptr);
    gemm_kernel<false><<<ggrid, 512>>>(nullptr, bufB, W2, b2, bufA, WIDTH);
    rnn_kernel<false, true><<<2 * BATCH, 256>>>(bufA, U2, nullptr,
                                                Wd, bd, out);

    (void)in_sizes; (void)n_in; (void)out_size;
}